// round 6
// baseline (speedup 1.0000x reference)
#include <cuda_runtime.h>

#define NN 8192
#define CC 128
#define FULLMASK 0xFFFFFFFFu
#define CAP 128
#define BM 64
#define SCAN_BLOCKS 256

// ---- scratch ----
__device__ float g_h[NN * CC];
__device__ float g_hx[NN * CC];        // dense-half partial (X @ Wc^T)
__device__ int   g_degi[NN];
__device__ int   g_cnt[NN];
__device__ int   g_bkt[NN * CAP];
__device__ float g_BT[2 * CC * CC];    // [Wn^T ; Wc^T], K-major [256][128]
__device__ float g_sum[CC];
__device__ float g_sumsq[CC];

__device__ __forceinline__ void ffma2(unsigned long long& d, unsigned long long a, unsigned long long b) {
    asm("fma.rn.f32x2 %0, %1, %2, %0;" : "+l"(d) : "l"(a), "l"(b));
}
__device__ __forceinline__ unsigned long long pack2(float x) {
    unsigned long long r; asm("mov.b64 %0, {%1, %1};" : "=l"(r) : "f"(x)); return r;
}

// ---------------------------------------------------------------
__global__ void k_zero() {
    int idx = blockIdx.x * 256 + threadIdx.x;     // 16 blocks
#pragma unroll
    for (int r = 0; r < 2; ++r) {
        int i = idx * 2 + r;
        if (i < NN) { g_degi[i] = 0; g_cnt[i] = 0; }
    }
    if (idx < CC) { g_sum[idx] = 0.f; g_sumsq[idx] = 0.f; }
}

// ---------------------------------------------------------------
__global__ void k_prep(const float* __restrict__ Wn, const float* __restrict__ Wc) {
    __shared__ float s[32][33];
    int bid = blockIdx.x;                 // 32 blocks
    int m = bid >> 4;
    int t = bid & 15;
    int tr = (t >> 2) * 32;
    int tc = (t & 3) * 32;
    const float* src = m ? Wc : Wn;
    float* dst = g_BT + m * CC * CC;
    int x = threadIdx.x & 31;
    int y0 = threadIdx.x >> 5;
#pragma unroll
    for (int dy = 0; dy < 32; dy += 8)
        s[y0 + dy][x] = src[(tr + y0 + dy) * CC + tc + x];
    __syncthreads();
#pragma unroll
    for (int dy = 0; dy < 32; dy += 8)
        dst[(tc + y0 + dy) * CC + tr + x] = s[x][y0 + dy];
}

// ---------------------------------------------------------------
// Persistent scan: 256 blocks x 256 threads, MLP=8. Leaves SM headroom
// so k_gemmX can co-reside on the same SMs (true overlap).
__global__ void k_scan(const float4* __restrict__ A4) {
    const int lane = threadIdx.x & 31;
    const long stride = (long)SCAN_BLOCKS * 256;        // 65536
    long base = (long)blockIdx.x * 256 + threadIdx.x;

#pragma unroll 1
    for (int it = 0; it < 32; ++it, base += 8 * stride) {
        float4 v[8];
#pragma unroll
        for (int u = 0; u < 8; ++u) v[u] = __ldcs(&A4[base + (long)u * stride]);
#pragma unroll
        for (int u = 0; u < 8; ++u) {
            long qu = base + (long)u * stride;
            int e0 = v[u].x != 0.f, e1 = v[u].y != 0.f;
            int e2 = v[u].z != 0.f, e3 = v[u].w != 0.f;
            int cnt = e0 + e1 + e2 + e3;
            unsigned anyb = __ballot_sync(FULLMASK, cnt);
            if (!anyb) continue;
            int j = (int)(qu >> 11);
            int tot = __reduce_add_sync(FULLMASK, cnt);
            if (lane == 0) atomicAdd(&g_degi[j], tot);
            if (cnt) {
                int cbase = (int)(qu & 2047) * 4;
                float vv[4] = {v[u].x, v[u].y, v[u].z, v[u].w};
#pragma unroll
                for (int s = 0; s < 4; ++s) {
                    if (vv[s] != 0.f) {
                        int i = cbase + s;
                        int pos = atomicAdd(&g_cnt[i], 1);
                        if (pos < CAP) g_bkt[i * CAP + pos] = j;
                    }
                }
            }
        }
    }
}

// ---------------------------------------------------------------
// Dense half: g_hx = X @ Wc^T  (overlaps the scan)
__global__ void __launch_bounds__(512, 1)
k_gemmX(const float* __restrict__ X) {
    extern __shared__ float sh[];
    float* Bs = sh;                 // WcT: 16384 floats
    float* As = sh + CC * CC;       // X tile: 8192 floats

    const int tid = threadIdx.x;
    const int m0  = blockIdx.x * BM;

    {
        const float4* src = (const float4*)(g_BT + CC * CC);
        float4* dst = (float4*)Bs;
#pragma unroll
        for (int i = 0; i < 8; ++i) dst[tid + i * 512] = src[tid + i * 512];
        const float4* xs = (const float4*)(X + (size_t)m0 * CC);
        float4* ad = (float4*)As;
#pragma unroll
        for (int i = 0; i < 4; ++i) ad[tid + i * 512] = __ldg(xs + tid + i * 512);
    }
    __syncthreads();

    const int cg = tid & 63;
    const int rg = tid >> 6;
    unsigned long long acc[8];
#pragma unroll
    for (int r = 0; r < 8; ++r) acc[r] = 0ull;

    const float* bb = Bs + cg * 2;
    const float* ab = As + rg * 8 * CC;
#pragma unroll 2
    for (int kk = 0; kk < CC; kk += 4) {
        float4 a[8];
#pragma unroll
        for (int r = 0; r < 8; ++r) a[r] = *(const float4*)(ab + r * CC + kk);
#pragma unroll
        for (int j = 0; j < 4; ++j) {
            unsigned long long bp = *(const unsigned long long*)(bb + (kk + j) * CC);
            float av[8];
#pragma unroll
            for (int r = 0; r < 8; ++r)
                av[r] = (j == 0) ? a[r].x : (j == 1) ? a[r].y : (j == 2) ? a[r].z : a[r].w;
#pragma unroll
            for (int r = 0; r < 8; ++r)
                ffma2(acc[r], pack2(av[r]), bp);
        }
    }
#pragma unroll
    for (int r = 0; r < 8; ++r) {
        int m = m0 + rg * 8 + r;
        *(float2*)(g_hx + (size_t)m * CC + cg * 2) = *(float2*)&acc[r];
    }
}

// ---------------------------------------------------------------
// Sparse half: gather agg (2-row interleaved, MLP 8, broadcast index
// loads), acc = agg @ Wn^T, h = acc + hx + bias; BN stats.
__global__ void __launch_bounds__(512, 1)
k_gemmA(const float* __restrict__ X, const float* __restrict__ bn, const float* __restrict__ bc) {
    extern __shared__ float sh[];
    float* Bs = sh;                 // WnT: 16384 floats
    float* As = sh + CC * CC;       // agg tile: 8192 floats

    const int tid  = threadIdx.x;
    const int lane = tid & 31;
    const int wid  = tid >> 5;
    const int m0   = blockIdx.x * BM;
    const int cg = tid & 63;
    const int rg = tid >> 6;

    {
        const float4* src = (const float4*)g_BT;
        float4* dst = (float4*)Bs;
#pragma unroll
        for (int i = 0; i < 8; ++i) dst[tid + i * 512] = src[tid + i * 512];
    }

    // prefetch hx combine operands (L2-hot, independent of gather)
    float2 hx[8];
#pragma unroll
    for (int r = 0; r < 8; ++r)
        hx[r] = __ldg((const float2*)(g_hx + (size_t)(m0 + rg * 8 + r) * CC + cg * 2));

    // --- gather: warp handles rows wid*4..+3, processed in interleaved pairs ---
    const float4* X4 = (const float4*)X;
#pragma unroll 1
    for (int rp = 0; rp < 4; rp += 2) {
        const int rowA = wid * 4 + rp, rowB = rowA + 1;
        const int nodeA = m0 + rowA,   nodeB = m0 + rowB;
        int cA = g_cnt[nodeA]; cA = cA > CAP ? CAP : cA;
        int cB = g_cnt[nodeB]; cB = cB > CAP ? CAP : cB;
        int dA = g_degi[nodeA], dB = g_degi[nodeB];
        float rA = (dA > 0) ? (1.f / (float)dA) : 1.f;
        float rB = (dB > 0) ? (1.f / (float)dB) : 1.f;
        const int* bkA = g_bkt + nodeA * CAP;
        const int* bkB = g_bkt + nodeB * CAP;

        float4 aA = {0.f, 0.f, 0.f, 0.f};
        float4 aB = {0.f, 0.f, 0.f, 0.f};
        int mm = (cA < cB ? cA : cB) & ~3;
        int t = 0;
        for (; t < mm; t += 4) {
            int ja0 = __ldg(bkA + t),     ja1 = __ldg(bkA + t + 1);
            int ja2 = __ldg(bkA + t + 2), ja3 = __ldg(bkA + t + 3);
            int jb0 = __ldg(bkB + t),     jb1 = __ldg(bkB + t + 1);
            int jb2 = __ldg(bkB + t + 2), jb3 = __ldg(bkB + t + 3);
            float4 x0 = __ldg(X4 + (long)ja0 * 32 + lane);
            float4 x1 = __ldg(X4 + (long)ja1 * 32 + lane);
            float4 x2 = __ldg(X4 + (long)ja2 * 32 + lane);
            float4 x3 = __ldg(X4 + (long)ja3 * 32 + lane);
            float4 y0 = __ldg(X4 + (long)jb0 * 32 + lane);
            float4 y1 = __ldg(X4 + (long)jb1 * 32 + lane);
            float4 y2 = __ldg(X4 + (long)jb2 * 32 + lane);
            float4 y3 = __ldg(X4 + (long)jb3 * 32 + lane);
            aA.x += x0.x + x1.x + x2.x + x3.x;
            aA.y += x0.y + x1.y + x2.y + x3.y;
            aA.z += x0.z + x1.z + x2.z + x3.z;
            aA.w += x0.w + x1.w + x2.w + x3.w;
            aB.x += y0.x + y1.x + y2.x + y3.x;
            aB.y += y0.y + y1.y + y2.y + y3.y;
            aB.z += y0.z + y1.z + y2.z + y3.z;
            aB.w += y0.w + y1.w + y2.w + y3.w;
        }
        int tB = t;
        for (; t + 4 <= cA; t += 4) {
            int j0 = __ldg(bkA + t),     j1 = __ldg(bkA + t + 1);
            int j2 = __ldg(bkA + t + 2), j3 = __ldg(bkA + t + 3);
            float4 x0 = __ldg(X4 + (long)j0 * 32 + lane);
            float4 x1 = __ldg(X4 + (long)j1 * 32 + lane);
            float4 x2 = __ldg(X4 + (long)j2 * 32 + lane);
            float4 x3 = __ldg(X4 + (long)j3 * 32 + lane);
            aA.x += x0.x + x1.x + x2.x + x3.x;
            aA.y += x0.y + x1.y + x2.y + x3.y;
            aA.z += x0.z + x1.z + x2.z + x3.z;
            aA.w += x0.w + x1.w + x2.w + x3.w;
        }
        for (; t < cA; ++t) {
            int j = __ldg(bkA + t);
            float4 x = __ldg(X4 + (long)j * 32 + lane);
            aA.x += x.x; aA.y += x.y; aA.z += x.z; aA.w += x.w;
        }
        for (; tB + 4 <= cB; tB += 4) {
            int j0 = __ldg(bkB + tB),     j1 = __ldg(bkB + tB + 1);
            int j2 = __ldg(bkB + tB + 2), j3 = __ldg(bkB + tB + 3);
            float4 y0 = __ldg(X4 + (long)j0 * 32 + lane);
            float4 y1 = __ldg(X4 + (long)j1 * 32 + lane);
            float4 y2 = __ldg(X4 + (long)j2 * 32 + lane);
            float4 y3 = __ldg(X4 + (long)j3 * 32 + lane);
            aB.x += y0.x + y1.x + y2.x + y3.x;
            aB.y += y0.y + y1.y + y2.y + y3.y;
            aB.z += y0.z + y1.z + y2.z + y3.z;
            aB.w += y0.w + y1.w + y2.w + y3.w;
        }
        for (; tB < cB; ++tB) {
            int j = __ldg(bkB + tB);
            float4 y = __ldg(X4 + (long)j * 32 + lane);
            aB.x += y.x; aB.y += y.y; aB.z += y.z; aB.w += y.w;
        }
        aA.x *= rA; aA.y *= rA; aA.z *= rA; aA.w *= rA;
        aB.x *= rB; aB.y *= rB; aB.z *= rB; aB.w *= rB;
        *(float4*)(As + (size_t)rowA * CC + lane * 4) = aA;
        *(float4*)(As + (size_t)rowB * CC + lane * 4) = aB;
    }
    __syncthreads();

    unsigned long long acc[8];
#pragma unroll
    for (int r = 0; r < 8; ++r) acc[r] = 0ull;

    const float* bb = Bs + cg * 2;
    const float* ab = As + rg * 8 * CC;
#pragma unroll 2
    for (int kk = 0; kk < CC; kk += 4) {
        float4 a[8];
#pragma unroll
        for (int r = 0; r < 8; ++r) a[r] = *(const float4*)(ab + r * CC + kk);
#pragma unroll
        for (int j = 0; j < 4; ++j) {
            unsigned long long bp = *(const unsigned long long*)(bb + (kk + j) * CC);
            float av[8];
#pragma unroll
            for (int r = 0; r < 8; ++r)
                av[r] = (j == 0) ? a[r].x : (j == 1) ? a[r].y : (j == 2) ? a[r].z : a[r].w;
#pragma unroll
            for (int r = 0; r < 8; ++r)
                ffma2(acc[r], pack2(av[r]), bp);
        }
    }

    // ---- epilogue: combine, bias, stats ----
    __syncthreads();
    float* s_sum = sh;
    float* s_sq  = sh + CC;
    if (tid < CC) { s_sum[tid] = 0.f; s_sq[tid] = 0.f; }
    __syncthreads();

    float b0 = bn[cg * 2] + bc[cg * 2];
    float b1 = bn[cg * 2 + 1] + bc[cg * 2 + 1];

    float ps0 = 0.f, ps1 = 0.f, pq0 = 0.f, pq1 = 0.f;
#pragma unroll
    for (int r = 0; r < 8; ++r) {
        int m = m0 + rg * 8 + r;
        float2 p = *(float2*)&acc[r];
        float h0 = p.x + hx[r].x + b0, h1 = p.y + hx[r].y + b1;
        ps0 += h0; ps1 += h1;
        pq0 += h0 * h0; pq1 += h1 * h1;
        float2 hv = {h0, h1};
        *(float2*)(g_h + (size_t)m * CC + cg * 2) = hv;
    }
    atomicAdd(&s_sum[cg * 2], ps0);
    atomicAdd(&s_sum[cg * 2 + 1], ps1);
    atomicAdd(&s_sq[cg * 2], pq0);
    atomicAdd(&s_sq[cg * 2 + 1], pq1);
    __syncthreads();
    if (tid < CC) {
        atomicAdd(&g_sum[tid],   s_sum[tid]);
        atomicAdd(&g_sumsq[tid], s_sq[tid]);
    }
}

// ---------------------------------------------------------------
__global__ void k_norm(const float* __restrict__ gamma, const float* __restrict__ beta,
                       float* __restrict__ out) {
    const int tid = blockIdx.x * blockDim.x + threadIdx.x;
    const int c0 = (tid & 31) * 4;
    const float invN = 1.f / (float)NN;
    float scale[4], shift[4];
#pragma unroll
    for (int i = 0; i < 4; ++i) {
        int c = c0 + i;
        float mu  = g_sum[c] * invN;
        float var = fmaxf(g_sumsq[c] * invN - mu * mu, 0.f);
        float inv = rsqrtf(var + 1e-5f);
        float sc = __ldg(gamma + c) * inv;
        scale[i] = sc;
        shift[i] = __ldg(beta + c) - mu * sc;
    }
    const float4* hp = (const float4*)g_h;
    float4* op = (float4*)out;
#pragma unroll
    for (int u = 0; u < 2; ++u) {
        int idx = tid + u * 131072;
        float4 h = __ldcs(hp + idx);
        float4 o;
        o.x = fmaxf(fmaf(h.x, scale[0], shift[0]), 0.f);
        o.y = fmaxf(fmaf(h.y, scale[1], shift[1]), 0.f);
        o.z = fmaxf(fmaf(h.z, scale[2], shift[2]), 0.f);
        o.w = fmaxf(fmaf(h.w, scale[3], shift[3]), 0.f);
        op[idx] = o;
    }
}

// ---------------------------------------------------------------
extern "C" void kernel_launch(void* const* d_in, const int* in_sizes, int n_in,
                              void* d_out, int out_size) {
    const float* Xf    = (const float*)d_in[0];
    const float* A     = (const float*)d_in[1];
    const float* Wn    = (const float*)d_in[2];
    const float* bn    = (const float*)d_in[3];
    const float* Wc    = (const float*)d_in[4];
    const float* bc    = (const float*)d_in[5];
    const float* gamma = (const float*)d_in[6];
    const float* beta  = (const float*)d_in[7];
    if (in_sizes[0] > in_sizes[1]) { const float* t = Xf; Xf = A; A = t; }

    float* out = (float*)d_out;

    static cudaStream_t s2 = []() {
        cudaStream_t s; cudaStreamCreateWithFlags(&s, cudaStreamNonBlocking); return s;
    }();
    static cudaEvent_t evF = []() {
        cudaEvent_t e; cudaEventCreateWithFlags(&e, cudaEventDisableTiming); return e;
    }();
    static cudaEvent_t evJ = []() {
        cudaEvent_t e; cudaEventCreateWithFlags(&e, cudaEventDisableTiming); return e;
    }();
    static bool attr_done = []() {
        size_t smem = (size_t)(CC * CC + BM * CC) * sizeof(float);   // 96KB
        cudaFuncSetAttribute(k_gemmX, cudaFuncAttributeMaxDynamicSharedMemorySize, (int)smem);
        cudaFuncSetAttribute(k_gemmA, cudaFuncAttributeMaxDynamicSharedMemorySize, (int)smem);
        return true;
    }();
    (void)attr_done;

    const size_t smem = (size_t)(CC * CC + BM * CC) * sizeof(float);

    // fork: scan path on s2 (persistent, leaves SM headroom for gemmX)
    cudaEventRecord(evF, 0);
    cudaStreamWaitEvent(s2, evF, 0);
    k_zero<<<16, 256, 0, s2>>>();
    k_scan<<<SCAN_BLOCKS, 256, 0, s2>>>((const float4*)A);
    cudaEventRecord(evJ, s2);

    // main stream: weight transpose + dense half (co-resides with scan)
    k_prep<<<32, 256>>>(Wn, Wc);
    k_gemmX<<<NN / BM, 512, smem>>>(Xf);

    // join, then sparse half + norm
    cudaStreamWaitEvent(0, evJ, 0);
    k_gemmA<<<NN / BM, 512, smem>>>(Xf, bn, bc);
    k_norm<<<512, 256>>>(gamma, beta, out);
}

// round 7
// speedup vs baseline: 1.0941x; 1.0941x over previous
#include <cuda_runtime.h>

#define NN 8192
#define CC 128
#define FULLMASK 0xFFFFFFFFu
#define CAP 128
#define AST 66                 // transposed A-tile stride (rows 64 + pad 2)

// ---- scratch ----
__device__ float g_h[NN * CC];
__device__ int   g_degi[NN];
__device__ int   g_cnt[NN];
__device__ int   g_bkt[NN * CAP];
__device__ float g_BT[2 * CC * CC];    // [Wn^T ; Wc^T], K-major [256][128]
__device__ float g_sum[CC];
__device__ float g_sumsq[CC];

__device__ __forceinline__ void ffma2(unsigned long long& d, unsigned long long a, unsigned long long b) {
    asm("fma.rn.f32x2 %0, %1, %2, %0;" : "+l"(d) : "l"(a), "l"(b));
}
__device__ __forceinline__ unsigned long long pack2(float x) {
    unsigned long long r; asm("mov.b64 %0, {%1, %1};" : "=l"(r) : "f"(x)); return r;
}

// ---------------------------------------------------------------
// Fused: transpose Wn,Wc into g_BT (blocks 0..31) + zero counters (32..47)
__global__ void k_prep(const float* __restrict__ Wn, const float* __restrict__ Wc) {
    int bid = blockIdx.x;
    if (bid < 32) {
        __shared__ float s[32][33];
        int m = bid >> 4;
        int t = bid & 15;
        int tr = (t >> 2) * 32;
        int tc = (t & 3) * 32;
        const float* src = m ? Wc : Wn;
        float* dst = g_BT + m * CC * CC;
        int x = threadIdx.x & 31;
        int y0 = threadIdx.x >> 5;
#pragma unroll
        for (int dy = 0; dy < 32; dy += 8)
            s[y0 + dy][x] = src[(tr + y0 + dy) * CC + tc + x];
        __syncthreads();
#pragma unroll
        for (int dy = 0; dy < 32; dy += 8)
            dst[(tc + y0 + dy) * CC + tr + x] = s[x][y0 + dy];
    } else {
        int idx = (bid - 32) * 256 + threadIdx.x;
#pragma unroll
        for (int r = 0; r < 2; ++r) {
            int i = idx * 2 + r;
            if (i < NN) { g_degi[i] = 0; g_cnt[i] = 0; }
        }
        if (idx < CC) { g_sum[idx] = 0.f; g_sumsq[idx] = 0.f; }
    }
}

// ---------------------------------------------------------------
// Scan adjacency (2048 blocks, MLP 4 — the proven DRAM-floor config).
__global__ void k_scan(const float4* __restrict__ A4) {
    const int lane = threadIdx.x & 31;
    const long stride = (long)gridDim.x * blockDim.x;
    const long total = (long)NN * 2048;

    for (long q0 = (long)blockIdx.x * blockDim.x + threadIdx.x; q0 < total; q0 += 4 * stride) {
        float4 v[4];
#pragma unroll
        for (int u = 0; u < 4; ++u) v[u] = __ldcs(&A4[q0 + (long)u * stride]);
#pragma unroll
        for (int u = 0; u < 4; ++u) {
            long qu = q0 + (long)u * stride;
            int e0 = v[u].x != 0.f, e1 = v[u].y != 0.f;
            int e2 = v[u].z != 0.f, e3 = v[u].w != 0.f;
            int cnt = e0 + e1 + e2 + e3;
            unsigned anyb = __ballot_sync(FULLMASK, cnt);
            if (!anyb) continue;
            int j = (int)(qu >> 11);
            int tot = __reduce_add_sync(FULLMASK, cnt);
            if (lane == 0) atomicAdd(&g_degi[j], tot);
            if (cnt) {
                int cbase = (int)(qu & 2047) * 4;
                float vv[4] = {v[u].x, v[u].y, v[u].z, v[u].w};
#pragma unroll
                for (int s = 0; s < 4; ++s) {
                    if (vv[s] != 0.f) {
                        int i = cbase + s;
                        int pos = atomicAdd(&g_cnt[i], 1);
                        if (pos < CAP) g_bkt[i * CAP + pos] = j;
                    }
                }
            }
        }
    }
}

// ---------------------------------------------------------------
// Fused gather + GEMM + BN stats. Block = 64 rows x 64 cols, 256 threads,
// 99KB smem -> 2 blocks/SM (grid 256). A tile kept TRANSPOSED in smem so
// row-pairs load as packed f32x2 operands (no dup-movs on the A side).
__global__ void __launch_bounds__(256, 2)
k_gemm(const float* __restrict__ X, const float* __restrict__ bn, const float* __restrict__ bc) {
    extern __shared__ float sh[];
    float* Bs = sh;                   // [256][64] column slice (64KB)
    float* As = sh + 256 * 64;        // [128][AST] transposed A tile (~33KB)

    const int tid  = threadIdx.x;
    const int lane = tid & 31;
    const int wid  = tid >> 5;        // 0..7; rows wid*8 .. wid*8+7
    const int tc   = tid & 31;        // local col pair (cols tc*2, tc*2+1)
    const int m0   = (blockIdx.x >> 1) * 64;
    const int c0   = (blockIdx.x & 1) * 64;

    // --- load B column slice ---
#pragma unroll
    for (int i = 0; i < 16; ++i) {
        int idx = tid + i * 256;              // 0..4095
        int k = idx >> 4, cc = (idx & 15) * 4;
        *(float4*)(Bs + k * 64 + cc) = *(const float4*)(g_BT + k * CC + c0 + cc);
    }

    // --- gather agg rows (interleaved pairs, MLP 8), store transposed ---
    const float4* X4 = (const float4*)X;
#pragma unroll 1
    for (int rp = 0; rp < 8; rp += 2) {
        const int rowA = wid * 8 + rp, rowB = rowA + 1;
        const int nodeA = m0 + rowA,   nodeB = m0 + rowB;
        int cA = g_cnt[nodeA]; cA = cA > CAP ? CAP : cA;
        int cB = g_cnt[nodeB]; cB = cB > CAP ? CAP : cB;
        int dA = g_degi[nodeA], dB = g_degi[nodeB];
        float rA = (dA > 0) ? (1.f / (float)dA) : 1.f;
        float rB = (dB > 0) ? (1.f / (float)dB) : 1.f;
        const int* bkA = g_bkt + nodeA * CAP;
        const int* bkB = g_bkt + nodeB * CAP;

        float4 aA = {0.f, 0.f, 0.f, 0.f};
        float4 aB = {0.f, 0.f, 0.f, 0.f};
        int mm = (cA < cB ? cA : cB) & ~3;
        int t = 0;
        for (; t < mm; t += 4) {
            int ja0 = __ldg(bkA + t),     ja1 = __ldg(bkA + t + 1);
            int ja2 = __ldg(bkA + t + 2), ja3 = __ldg(bkA + t + 3);
            int jb0 = __ldg(bkB + t),     jb1 = __ldg(bkB + t + 1);
            int jb2 = __ldg(bkB + t + 2), jb3 = __ldg(bkB + t + 3);
            float4 x0 = __ldg(X4 + (long)ja0 * 32 + lane);
            float4 x1 = __ldg(X4 + (long)ja1 * 32 + lane);
            float4 x2 = __ldg(X4 + (long)ja2 * 32 + lane);
            float4 x3 = __ldg(X4 + (long)ja3 * 32 + lane);
            float4 y0 = __ldg(X4 + (long)jb0 * 32 + lane);
            float4 y1 = __ldg(X4 + (long)jb1 * 32 + lane);
            float4 y2 = __ldg(X4 + (long)jb2 * 32 + lane);
            float4 y3 = __ldg(X4 + (long)jb3 * 32 + lane);
            aA.x += x0.x + x1.x + x2.x + x3.x;
            aA.y += x0.y + x1.y + x2.y + x3.y;
            aA.z += x0.z + x1.z + x2.z + x3.z;
            aA.w += x0.w + x1.w + x2.w + x3.w;
            aB.x += y0.x + y1.x + y2.x + y3.x;
            aB.y += y0.y + y1.y + y2.y + y3.y;
            aB.z += y0.z + y1.z + y2.z + y3.z;
            aB.w += y0.w + y1.w + y2.w + y3.w;
        }
        int tB = t;
        for (; t < cA; ++t) {
            int j = __ldg(bkA + t);
            float4 x = __ldg(X4 + (long)j * 32 + lane);
            aA.x += x.x; aA.y += x.y; aA.z += x.z; aA.w += x.w;
        }
        for (; tB < cB; ++tB) {
            int j = __ldg(bkB + tB);
            float4 y = __ldg(X4 + (long)j * 32 + lane);
            aB.x += y.x; aB.y += y.y; aB.z += y.z; aB.w += y.w;
        }
        aA.x *= rA; aA.y *= rA; aA.z *= rA; aA.w *= rA;
        aB.x *= rB; aB.y *= rB; aB.z *= rB; aB.w *= rB;
        // transposed stores: As[k][row]
        As[(lane * 4 + 0) * AST + rowA] = aA.x;
        As[(lane * 4 + 1) * AST + rowA] = aA.y;
        As[(lane * 4 + 2) * AST + rowA] = aA.z;
        As[(lane * 4 + 3) * AST + rowA] = aA.w;
        As[(lane * 4 + 0) * AST + rowB] = aB.x;
        As[(lane * 4 + 1) * AST + rowB] = aB.y;
        As[(lane * 4 + 2) * AST + rowB] = aB.z;
        As[(lane * 4 + 3) * AST + rowB] = aB.w;
    }
    __syncthreads();

    // --- mainloop: acc packed over row pairs ---
    unsigned long long acc[4][2];
#pragma unroll
    for (int rp = 0; rp < 4; ++rp) { acc[rp][0] = 0ull; acc[rp][1] = 0ull; }

#pragma unroll 1
    for (int half = 0; half < 2; ++half) {
        const float* bb = Bs + half * 128 * 64 + tc * 2;
#pragma unroll 4
        for (int k = 0; k < 128; ++k) {
            const float2* ap = (const float2*)(As + k * AST + wid * 8);  // broadcast
            float2 p0 = ap[0], p1 = ap[1], p2 = ap[2], p3 = ap[3];
            float2 b = *(const float2*)(bb + k * 64);
            unsigned long long bd0 = pack2(b.x);
            unsigned long long bd1 = pack2(b.y);
            ffma2(acc[0][0], *(unsigned long long*)&p0, bd0);
            ffma2(acc[0][1], *(unsigned long long*)&p0, bd1);
            ffma2(acc[1][0], *(unsigned long long*)&p1, bd0);
            ffma2(acc[1][1], *(unsigned long long*)&p1, bd1);
            ffma2(acc[2][0], *(unsigned long long*)&p2, bd0);
            ffma2(acc[2][1], *(unsigned long long*)&p2, bd1);
            ffma2(acc[3][0], *(unsigned long long*)&p3, bd0);
            ffma2(acc[3][1], *(unsigned long long*)&p3, bd1);
        }
        if (half == 0) {
            // restage As with X tile (transposed)
            __syncthreads();
            const float4* xs = (const float4*)(X + (size_t)m0 * CC);
#pragma unroll
            for (int i = 0; i < 8; ++i) {
                int idx = tid + i * 256;           // 0..2047
                int row = idx >> 5, kq = (idx & 31) * 4;
                float4 v = __ldg(xs + idx);
                As[(kq + 0) * AST + row] = v.x;
                As[(kq + 1) * AST + row] = v.y;
                As[(kq + 2) * AST + row] = v.z;
                As[(kq + 3) * AST + row] = v.w;
            }
            __syncthreads();
        }
    }

    // --- epilogue: bias, write h, BN stats ---
    __syncthreads();
    float* s_sum = sh;
    float* s_sq  = sh + 64;
    if (tid < 64) { s_sum[tid] = 0.f; s_sq[tid] = 0.f; }
    __syncthreads();

    float b0 = __ldg(bn + c0 + tc * 2)     + __ldg(bc + c0 + tc * 2);
    float b1 = __ldg(bn + c0 + tc * 2 + 1) + __ldg(bc + c0 + tc * 2 + 1);

    float ps0 = 0.f, ps1 = 0.f, pq0 = 0.f, pq1 = 0.f;
#pragma unroll
    for (int rp = 0; rp < 4; ++rp) {
        float2 pc0 = *(float2*)&acc[rp][0];    // col0, rows (even, odd)
        float2 pc1 = *(float2*)&acc[rp][1];    // col1, rows (even, odd)
        float hE0 = pc0.x + b0, hE1 = pc1.x + b1;
        float hO0 = pc0.y + b0, hO1 = pc1.y + b1;
        ps0 += hE0 + hO0; ps1 += hE1 + hO1;
        pq0 += hE0 * hE0 + hO0 * hO0;
        pq1 += hE1 * hE1 + hO1 * hO1;
        int mE = m0 + wid * 8 + rp * 2;
        float2 vE = {hE0, hE1};
        float2 vO = {hO0, hO1};
        *(float2*)(g_h + (size_t)mE * CC + c0 + tc * 2) = vE;
        *(float2*)(g_h + (size_t)(mE + 1) * CC + c0 + tc * 2) = vO;
    }
    atomicAdd(&s_sum[tc * 2], ps0);
    atomicAdd(&s_sum[tc * 2 + 1], ps1);
    atomicAdd(&s_sq[tc * 2], pq0);
    atomicAdd(&s_sq[tc * 2 + 1], pq1);
    __syncthreads();
    if (tid < 64) {
        atomicAdd(&g_sum[c0 + tid],   s_sum[tid]);
        atomicAdd(&g_sumsq[c0 + tid], s_sq[tid]);
    }
}

// ---------------------------------------------------------------
__global__ void k_norm(const float* __restrict__ gamma, const float* __restrict__ beta,
                       float* __restrict__ out) {
    const int tid = blockIdx.x * blockDim.x + threadIdx.x;
    const int c0 = (tid & 31) * 4;
    const float invN = 1.f / (float)NN;
    float scale[4], shift[4];
#pragma unroll
    for (int i = 0; i < 4; ++i) {
        int c = c0 + i;
        float mu  = g_sum[c] * invN;
        float var = fmaxf(g_sumsq[c] * invN - mu * mu, 0.f);
        float inv = rsqrtf(var + 1e-5f);
        float sc = __ldg(gamma + c) * inv;
        scale[i] = sc;
        shift[i] = __ldg(beta + c) - mu * sc;
    }
    const float4* hp = (const float4*)g_h;
    float4* op = (float4*)out;
#pragma unroll
    for (int u = 0; u < 2; ++u) {
        int idx = tid + u * 131072;
        float4 h = __ldcs(hp + idx);
        float4 o;
        o.x = fmaxf(fmaf(h.x, scale[0], shift[0]), 0.f);
        o.y = fmaxf(fmaf(h.y, scale[1], shift[1]), 0.f);
        o.z = fmaxf(fmaf(h.z, scale[2], shift[2]), 0.f);
        o.w = fmaxf(fmaf(h.w, scale[3], shift[3]), 0.f);
        op[idx] = o;
    }
}

// ---------------------------------------------------------------
extern "C" void kernel_launch(void* const* d_in, const int* in_sizes, int n_in,
                              void* d_out, int out_size) {
    const float* Xf    = (const float*)d_in[0];
    const float* A     = (const float*)d_in[1];
    const float* Wn    = (const float*)d_in[2];
    const float* bn    = (const float*)d_in[3];
    const float* Wc    = (const float*)d_in[4];
    const float* bc    = (const float*)d_in[5];
    const float* gamma = (const float*)d_in[6];
    const float* beta  = (const float*)d_in[7];
    if (in_sizes[0] > in_sizes[1]) { const float* t = Xf; Xf = A; A = t; }

    float* out = (float*)d_out;

    static bool attr_done = []() {
        size_t smem = (size_t)(256 * 64 + 128 * AST) * sizeof(float);   // ~99KB
        cudaFuncSetAttribute(k_gemm, cudaFuncAttributeMaxDynamicSharedMemorySize, (int)smem);
        return true;
    }();
    (void)attr_done;

    const size_t smem = (size_t)(256 * 64 + 128 * AST) * sizeof(float);

    k_prep<<<48, 256>>>(Wn, Wc);
    k_scan<<<2048, 256>>>((const float4*)A);
    k_gemm<<<256, 256, smem>>>(Xf, bn, bc);
    k_norm<<<512, 256>>>(gamma, beta, out);
}

// round 8
// speedup vs baseline: 1.5694x; 1.4344x over previous
#include <cuda_runtime.h>

#define NN 8192
#define CC 128
#define FULLMASK 0xFFFFFFFFu
#define CAP 128
#define BM 64

// ---- scratch ----
__device__ float g_h[NN * CC];
__device__ int   g_degi[NN];
__device__ int   g_cnt[NN];
__device__ int   g_bkt[NN * CAP];
__device__ float g_BT[2 * CC * CC];    // [Wn^T ; Wc^T], K-major [256][128]
__device__ float g_sum[CC];
__device__ float g_sumsq[CC];
__device__ float g_scale[CC];
__device__ float g_shift[CC];

__device__ __forceinline__ void ffma2(unsigned long long& d, unsigned long long a, unsigned long long b) {
    asm("fma.rn.f32x2 %0, %1, %2, %0;" : "+l"(d) : "l"(a), "l"(b));
}
__device__ __forceinline__ unsigned long long pack2(float x) {
    unsigned long long r; asm("mov.b64 %0, {%1, %1};" : "=l"(r) : "f"(x)); return r;
}

// ---------------------------------------------------------------
// Fused: transpose Wn,Wc into g_BT (blocks 0..31) + zero counters (32..47)
__global__ void k_prep(const float* __restrict__ Wn, const float* __restrict__ Wc) {
    int bid = blockIdx.x;
    if (bid < 32) {
        __shared__ float s[32][33];
        int m = bid >> 4;
        int t = bid & 15;
        int tr = (t >> 2) * 32;
        int tc = (t & 3) * 32;
        const float* src = m ? Wc : Wn;
        float* dst = g_BT + m * CC * CC;
        int x = threadIdx.x & 31;
        int y0 = threadIdx.x >> 5;
#pragma unroll
        for (int dy = 0; dy < 32; dy += 8)
            s[y0 + dy][x] = src[(tr + y0 + dy) * CC + tc + x];
        __syncthreads();
#pragma unroll
        for (int dy = 0; dy < 32; dy += 8)
            dst[(tc + y0 + dy) * CC + tr + x] = s[x][y0 + dy];
    } else {
        int idx = (bid - 32) * 256 + threadIdx.x;
#pragma unroll
        for (int r = 0; r < 2; ++r) {
            int i = idx * 2 + r;
            if (i < NN) { g_degi[i] = 0; g_cnt[i] = 0; }
        }
        if (idx < CC) { g_sum[idx] = 0.f; g_sumsq[idx] = 0.f; }
    }
}

// ---------------------------------------------------------------
// Scan adjacency (2048 blocks, MLP 4 — proven DRAM-floor config).
__global__ void k_scan(const float4* __restrict__ A4) {
    const int lane = threadIdx.x & 31;
    const long stride = (long)gridDim.x * blockDim.x;
    const long total = (long)NN * 2048;

    for (long q0 = (long)blockIdx.x * blockDim.x + threadIdx.x; q0 < total; q0 += 4 * stride) {
        float4 v[4];
#pragma unroll
        for (int u = 0; u < 4; ++u) v[u] = __ldcs(&A4[q0 + (long)u * stride]);
#pragma unroll
        for (int u = 0; u < 4; ++u) {
            long qu = q0 + (long)u * stride;
            int e0 = v[u].x != 0.f, e1 = v[u].y != 0.f;
            int e2 = v[u].z != 0.f, e3 = v[u].w != 0.f;
            int cnt = e0 + e1 + e2 + e3;
            unsigned anyb = __ballot_sync(FULLMASK, cnt);
            if (!anyb) continue;
            int j = (int)(qu >> 11);
            int tot = __reduce_add_sync(FULLMASK, cnt);
            if (lane == 0) atomicAdd(&g_degi[j], tot);
            if (cnt) {
                int cbase = (int)(qu & 2047) * 4;
                float vv[4] = {v[u].x, v[u].y, v[u].z, v[u].w};
#pragma unroll
                for (int s = 0; s < 4; ++s) {
                    if (vv[s] != 0.f) {
                        int i = cbase + s;
                        int pos = atomicAdd(&g_cnt[i], 1);
                        if (pos < CAP) g_bkt[i * CAP + pos] = j;
                    }
                }
            }
        }
    }
}

// ---------------------------------------------------------------
// Fused gather + GEMM + BN-stat epilogue (round-4 structure; 4x4 tile).
// 512 threads, 64 rows/block, B fully smem-resident (128KB), As 32KB.
__global__ void __launch_bounds__(512, 1)
k_gemm(const float* __restrict__ X, const float* __restrict__ bn, const float* __restrict__ bc) {
    extern __shared__ float sh[];
    float* Bs = sh;                 // 32768 floats (128KB)
    float* As = sh + 2 * CC * CC;   // 8192 floats (32KB)

    const int tid  = threadIdx.x;
    const int lane = tid & 31;
    const int wid  = tid >> 5;      // 16 warps
    const int m0   = blockIdx.x * BM;

    // --- load weights to smem ---
    {
        const float4* src = (const float4*)g_BT;
        float4* dst = (float4*)Bs;
#pragma unroll
        for (int i = 0; i < 16; ++i) dst[tid + i * 512] = src[tid + i * 512];
    }

    // --- gather agg rows: warp w -> rows w*4..w*4+3 (round-4 proven path) ---
    const float4* X4 = (const float4*)X;
#pragma unroll 1
    for (int r = 0; r < 4; ++r) {
        int row  = wid * 4 + r;
        int node = m0 + row;
        int cnt = g_cnt[node]; if (cnt > CAP) cnt = CAP;
        int dg  = g_degi[node];
        float rdeg = (dg > 0) ? (1.f / (float)dg) : 1.f;
        const int* bk = g_bkt + node * CAP;
        int nb[4];
#pragma unroll
        for (int w = 0; w < 4; ++w) nb[w] = (lane + 32 * w < cnt) ? bk[lane + 32 * w] : 0;

        float4 acc = {0.f, 0.f, 0.f, 0.f};
        int t = 0;
        for (; t + 4 <= cnt; t += 4) {
            int j0 = __shfl_sync(FULLMASK, nb[(t + 0) >> 5], (t + 0) & 31);
            int j1 = __shfl_sync(FULLMASK, nb[(t + 1) >> 5], (t + 1) & 31);
            int j2 = __shfl_sync(FULLMASK, nb[(t + 2) >> 5], (t + 2) & 31);
            int j3 = __shfl_sync(FULLMASK, nb[(t + 3) >> 5], (t + 3) & 31);
            float4 x0 = __ldg(X4 + (long)j0 * 32 + lane);
            float4 x1 = __ldg(X4 + (long)j1 * 32 + lane);
            float4 x2 = __ldg(X4 + (long)j2 * 32 + lane);
            float4 x3 = __ldg(X4 + (long)j3 * 32 + lane);
            acc.x += x0.x + x1.x + x2.x + x3.x;
            acc.y += x0.y + x1.y + x2.y + x3.y;
            acc.z += x0.z + x1.z + x2.z + x3.z;
            acc.w += x0.w + x1.w + x2.w + x3.w;
        }
        for (; t < cnt; ++t) {
            int j = __shfl_sync(FULLMASK, nb[t >> 5], t & 31);
            float4 x = __ldg(X4 + (long)j * 32 + lane);
            acc.x += x.x; acc.y += x.y; acc.z += x.z; acc.w += x.w;
        }
        acc.x *= rdeg; acc.y *= rdeg; acc.z *= rdeg; acc.w *= rdeg;
        *(float4*)(As + (size_t)row * CC + lane * 4) = acc;
    }
    __syncthreads();

    // --- mainloop: 4 rows x 4 cols per thread ---
    const int cg = tid & 31;        // cols cg*4 .. cg*4+3
    const int rg = tid >> 5;        // rows rg*4 .. rg*4+3 (== wid)
    unsigned long long acc[4][2];
#pragma unroll
    for (int r = 0; r < 4; ++r) { acc[r][0] = 0ull; acc[r][1] = 0ull; }

#pragma unroll 1
    for (int half = 0; half < 2; ++half) {
        const float* bb = Bs + half * CC * CC + cg * 4;
        const float* ab = As + rg * 4 * CC;
#pragma unroll 2
        for (int kk = 0; kk < CC; kk += 4) {
            float4 a[4];
#pragma unroll
            for (int r = 0; r < 4; ++r) a[r] = *(const float4*)(ab + r * CC + kk);
#pragma unroll
            for (int j = 0; j < 4; ++j) {
                ulonglong2 bp = *(const ulonglong2*)(bb + (kk + j) * CC);
                float av[4];
#pragma unroll
                for (int r = 0; r < 4; ++r)
                    av[r] = (j == 0) ? a[r].x : (j == 1) ? a[r].y : (j == 2) ? a[r].z : a[r].w;
#pragma unroll
                for (int r = 0; r < 4; ++r) {
                    unsigned long long ad = pack2(av[r]);
                    ffma2(acc[r][0], ad, bp.x);
                    ffma2(acc[r][1], ad, bp.y);
                }
            }
        }
        if (half == 0) {
            // stage X tile into As
            __syncthreads();
            const float4* xs = (const float4*)(X + (size_t)m0 * CC);
            float4* ad = (float4*)As;
#pragma unroll
            for (int i = 0; i < 4; ++i) ad[tid + i * 512] = __ldg(xs + tid + i * 512);
            __syncthreads();
        }
    }

    // --- epilogue: bias, write h, stats ---
    __syncthreads();
    float* s_sum = sh;
    float* s_sq  = sh + CC;
    if (tid < CC) { s_sum[tid] = 0.f; s_sq[tid] = 0.f; }
    __syncthreads();

    float bias[4];
#pragma unroll
    for (int c = 0; c < 4; ++c) bias[c] = __ldg(bn + cg * 4 + c) + __ldg(bc + cg * 4 + c);

    float psum[4] = {0, 0, 0, 0};
    float psq[4]  = {0, 0, 0, 0};
#pragma unroll
    for (int r = 0; r < 4; ++r) {
        int m = m0 + rg * 4 + r;
        float2 p0 = *(float2*)&acc[r][0];
        float2 p1 = *(float2*)&acc[r][1];
        float h[4] = {p0.x + bias[0], p0.y + bias[1], p1.x + bias[2], p1.y + bias[3]};
#pragma unroll
        for (int c = 0; c < 4; ++c) { psum[c] += h[c]; psq[c] += h[c] * h[c]; }
        float4 hv = {h[0], h[1], h[2], h[3]};
        *(float4*)(g_h + (size_t)m * CC + cg * 4) = hv;
    }
#pragma unroll
    for (int c = 0; c < 4; ++c) {
        atomicAdd(&s_sum[cg * 4 + c], psum[c]);
        atomicAdd(&s_sq[cg * 4 + c],  psq[c]);
    }
    __syncthreads();
    if (tid < CC) {
        atomicAdd(&g_sum[tid],   s_sum[tid]);
        atomicAdd(&g_sumsq[tid], s_sq[tid]);
    }
}

// ---------------------------------------------------------------
// Precompute per-channel scale/shift (kills per-thread MUFU in k_norm).
__global__ void k_stats(const float* __restrict__ gamma, const float* __restrict__ beta) {
    int c = threadIdx.x;
    const float invN = 1.f / (float)NN;
    float mu  = g_sum[c] * invN;
    float var = fmaxf(g_sumsq[c] * invN - mu * mu, 0.f);
    float inv = rsqrtf(var + 1e-5f);
    float sc = gamma[c] * inv;
    g_scale[c] = sc;
    g_shift[c] = beta[c] - mu * sc;
}

// ---------------------------------------------------------------
__global__ void k_norm(float* __restrict__ out) {
    const int tid = blockIdx.x * blockDim.x + threadIdx.x;   // 131072 threads
    const int c0 = (tid & 31) * 4;
    float4 sc = *(const float4*)(g_scale + c0);
    float4 sf = *(const float4*)(g_shift + c0);
    const float4* hp = (const float4*)g_h;
    float4* op = (float4*)out;
#pragma unroll
    for (int u = 0; u < 2; ++u) {
        int idx = tid + u * 131072;
        float4 h = __ldcs(hp + idx);
        float4 o;
        o.x = fmaxf(fmaf(h.x, sc.x, sf.x), 0.f);
        o.y = fmaxf(fmaf(h.y, sc.y, sf.y), 0.f);
        o.z = fmaxf(fmaf(h.z, sc.z, sf.z), 0.f);
        o.w = fmaxf(fmaf(h.w, sc.w, sf.w), 0.f);
        op[idx] = o;
    }
}

// ---------------------------------------------------------------
extern "C" void kernel_launch(void* const* d_in, const int* in_sizes, int n_in,
                              void* d_out, int out_size) {
    const float* Xf    = (const float*)d_in[0];
    const float* A     = (const float*)d_in[1];
    const float* Wn    = (const float*)d_in[2];
    const float* bn    = (const float*)d_in[3];
    const float* Wc    = (const float*)d_in[4];
    const float* bc    = (const float*)d_in[5];
    const float* gamma = (const float*)d_in[6];
    const float* beta  = (const float*)d_in[7];
    if (in_sizes[0] > in_sizes[1]) { const float* t = Xf; Xf = A; A = t; }

    float* out = (float*)d_out;

    static bool attr_done = []() {
        size_t smem = (size_t)(2 * CC * CC + BM * CC) * sizeof(float);   // 160KB
        cudaFuncSetAttribute(k_gemm, cudaFuncAttributeMaxDynamicSharedMemorySize, (int)smem);
        return true;
    }();
    (void)attr_done;

    const size_t smem = (size_t)(2 * CC * CC + BM * CC) * sizeof(float);

    k_prep<<<48, 256>>>(Wn, Wc);
    k_scan<<<2048, 256>>>((const float4*)A);
    k_gemm<<<NN / BM, 512, smem>>>(Xf, bn, bc);
    k_stats<<<1, 128>>>(gamma, beta);
    k_norm<<<512, 256>>>(out);
}